// round 4
// baseline (speedup 1.0000x reference)
#include <cuda_runtime.h>
#include <cuda_bf16.h>
#include <math.h>

// RoPE: x[B=16, S=8192, D=128] fp32, interleaved pairs, pos = arange(S)
// (token_positions is ignored by the reference).
//
// Single fused kernel. Block = 8 positions x 16 batches x 32 float4:
//   - 512 threads front-batch 8 independent float4 streaming loads (MLP=8)
//   - threads t<256 compute the 8x64 (cos,sin) table (2 sincosf each),
//     with w_f = theta^(-f/64) from double exp2 (matches reference fp32)
//   - after one barrier, rotate + streaming store.

#define B_      16
#define S_      8192
#define HALF    64
#define JPOS    8
#define THREADS 512

__global__ void __launch_bounds__(THREADS) rope_apply(
    const float4* __restrict__ x, float4* __restrict__ out)
{
    __shared__ float2 s_trig[JPOS][HALF];   // [pos-in-block][freq] = (cos,sin)

    int t  = threadIdx.x;
    int p0 = blockIdx.x * JPOS;

    int batch = t >> 5;            // 0..15
    int d4    = t & 31;            // float4 index within head dim
    size_t base = (size_t)batch * (S_ * 32) + (size_t)p0 * 32 + d4;

    // Front-batch 8 independent 16B streaming loads (one per position)
    float4 v[JPOS];
#pragma unroll
    for (int j = 0; j < JPOS; j++)
        v[j] = __ldcs(&x[base + (size_t)j * 32]);

    // 8 warps compute the 8x64 trig table while the loads are in flight
    if (t < 256) {
        int j0 = t >> 6;           // 0..3
        int f  = t & 63;
        const double LOG2_THETA = 13.287712379549449;  // log2(10000)
        double w = exp2(-((2.0 * (double)f) / 128.0) * LOG2_THETA);
        float wf = (float)w;       // == reference's fp32 inv_freq[f]
#pragma unroll
        for (int jj = 0; jj < 2; jj++) {
            int j = j0 + jj * 4;
            float ang = (float)(p0 + j) * wf;
            float s, c;
            sincosf(ang, &s, &c);
            s_trig[j][f] = make_float2(c, s);
        }
    }
    __syncthreads();

#pragma unroll
    for (int j = 0; j < JPOS; j++) {
        // (cos_{2*d4}, sin_{2*d4}, cos_{2*d4+1}, sin_{2*d4+1}) in one LDS.128
        float4 cs = reinterpret_cast<const float4*>(s_trig[j])[d4];
        float4 o;
        o.x = v[j].x * cs.x - v[j].y * cs.y;
        o.y = v[j].x * cs.y + v[j].y * cs.x;
        o.z = v[j].z * cs.z - v[j].w * cs.w;
        o.w = v[j].z * cs.w + v[j].w * cs.z;
        __stcs(&out[base + (size_t)j * 32], o);
    }
}

extern "C" void kernel_launch(void* const* d_in, const int* in_sizes, int n_in,
                              void* d_out, int out_size) {
    const float4* x = (const float4*)d_in[0];
    float4* out = (float4*)d_out;

    rope_apply<<<S_ / JPOS, THREADS>>>(x, out);   // 1024 blocks, single launch
}